// round 6
// baseline (speedup 1.0000x reference)
#include <cuda_runtime.h>

// Reference semantics: image (B,M,N,2) raw-reinterpreted as (2B, M, N) planes;
// flow2[p] = flow[p>>1]; out_flat[p*MN + y*N + x] = bilinear(view[p], x+dx, y+dy),
// zero outside bounds. Each thread: 4 consecutive pixels of one row, both planes.
// total = 64*384*384 = 9437184 = 9216 blocks * 256 threads * 4 pixels exactly.

#define MM 384
#define NN 384
#define MN (MM * NN)

__global__ __launch_bounds__(256) void warp_kernel(
    const float*  __restrict__ image,  // 2B*MN floats (raw)
    const float4* __restrict__ flow4,  // B*MN float2 viewed as float4 pairs
    float*        __restrict__ out,    // 2B*MN floats (raw)
    int total)                         // B*MN
{
    int tid  = blockIdx.x * blockDim.x + threadIdx.x;
    int base = tid * 4;                // first pixel index
    if (base >= total) return;

    // 4 consecutive pixels share y, b (row-aligned group)
    int x  = base % NN;
    int t  = base / NN;
    int y  = t % MM;
    int b  = t / MM;

    // flow for 4 pixels: 8 floats = 2 float4 (32B-aligned)
    float4 fA = __ldg(&flow4[tid * 2]);
    float4 fB = __ldg(&flow4[tid * 2 + 1]);
    float fx[4] = {fA.x, fA.z, fB.x, fB.z};
    float fy[4] = {fA.y, fA.w, fB.y, fB.w};

    int   o00[4], o01[4], o10[4], o11[4];
    float w00[4], w01[4], w10[4], w11[4];

#pragma unroll
    for (int i = 0; i < 4; i++) {
        float xs = (float)(x + i) + fx[i];
        float ys = (float)y + fy[i];

        float x0f = floorf(xs);
        float y0f = floorf(ys);
        float wx = xs - x0f;
        float wy = ys - y0f;
        int x0 = (int)x0f;
        int y0 = (int)y0f;
        int x1 = x0 + 1;
        int y1 = y0 + 1;

        float wxm0 = ((unsigned)x0 < (unsigned)NN) ? (1.0f - wx) : 0.0f;
        float wxm1 = ((unsigned)x1 < (unsigned)NN) ? wx : 0.0f;
        float wym0 = ((unsigned)y0 < (unsigned)MM) ? (1.0f - wy) : 0.0f;
        float wym1 = ((unsigned)y1 < (unsigned)MM) ? wy : 0.0f;

        int xc0 = min(max(x0, 0), NN - 1);
        int xc1 = min(max(x1, 0), NN - 1);
        int yc0 = min(max(y0, 0), MM - 1);
        int yc1 = min(max(y1, 0), MM - 1);

        o00[i] = yc0 * NN + xc0;
        o01[i] = yc0 * NN + xc1;
        o10[i] = yc1 * NN + xc0;
        o11[i] = yc1 * NN + xc1;
        w00[i] = wym0 * wxm0;
        w01[i] = wym0 * wxm1;
        w10[i] = wym1 * wxm0;
        w11[i] = wym1 * wxm1;
    }

    const float* pA = image + (size_t)(2 * b) * MN;
    const float* pB = pA + MN;

    // issue all 32 gathers unconditionally; ptxas front-batches for MLP
    float vA00[4], vA01[4], vA10[4], vA11[4];
    float vB00[4], vB01[4], vB10[4], vB11[4];
#pragma unroll
    for (int i = 0; i < 4; i++) {
        vA00[i] = __ldg(pA + o00[i]);
        vA01[i] = __ldg(pA + o01[i]);
        vA10[i] = __ldg(pA + o10[i]);
        vA11[i] = __ldg(pA + o11[i]);
        vB00[i] = __ldg(pB + o00[i]);
        vB01[i] = __ldg(pB + o01[i]);
        vB10[i] = __ldg(pB + o10[i]);
        vB11[i] = __ldg(pB + o11[i]);
    }

    float4 resA, resB;
    float* rA = (float*)&resA;
    float* rB = (float*)&resB;
#pragma unroll
    for (int i = 0; i < 4; i++) {
        rA[i] = vA00[i] * w00[i] + vA01[i] * w01[i]
              + vA10[i] * w10[i] + vA11[i] * w11[i];
        rB[i] = vB00[i] * w00[i] + vB01[i] * w01[i]
              + vB10[i] * w10[i] + vB11[i] * w11[i];
    }

    size_t po = (size_t)(2 * b) * MN + y * NN + x;   // 4-aligned
    *reinterpret_cast<float4*>(out + po)      = resA;
    *reinterpret_cast<float4*>(out + po + MN) = resB;
}

extern "C" void kernel_launch(void* const* d_in, const int* in_sizes, int n_in,
                              void* d_out, int out_size)
{
    const float*  image = (const float*)d_in[0];
    const float4* flow4 = (const float4*)d_in[1];
    float* out = (float*)d_out;

    int total = out_size / 2;                 // B*M*N pixels
    int threads = 256;
    int blocks = (total / 4 + threads - 1) / threads;   // exact: 9216
    warp_kernel<<<blocks, threads>>>(image, flow4, out, total);
}

// round 7
// speedup vs baseline: 1.1801x; 1.1801x over previous
#include <cuda_runtime.h>

// Reference semantics: image (B,M,N,2) raw-reinterpreted as (2B, M, N) planes;
// flow2[p] = flow[p>>1]; out_flat[p*MN + y*N + x] = bilinear(view[p], x+dx, y+dy),
// zero outside bounds. One thread handles ILP=4 block-strided pixels (lanes stay
// on consecutive x for tight gather wavefronts), both planes per pixel.
// total = 64*384*384 = 9216 blocks * 256 threads * 4 (exact, no tail).

#define MM 384
#define NN 384
#define MN (MM * NN)
#define ILP 4

__global__ __launch_bounds__(256) void warp_kernel(
    const float*  __restrict__ image,  // 2B*MN floats (raw)
    const float2* __restrict__ flow,   // B*MN float2
    float*        __restrict__ out)    // 2B*MN floats (raw)
{
    int base = blockIdx.x * (blockDim.x * ILP) + threadIdx.x;

    int   idx[ILP];
    int   o00[ILP], o01[ILP], o10[ILP], o11[ILP];
    float w00[ILP], w01[ILP], w10[ILP], w11[ILP];
    size_t pbase[ILP];
    float2 f[ILP];

#pragma unroll
    for (int i = 0; i < ILP; i++) {
        idx[i] = base + i * 256;
        f[i] = __ldcs(&flow[idx[i]]);   // streaming: no reuse
    }

#pragma unroll
    for (int i = 0; i < ILP; i++) {
        int x = idx[i] % NN;
        int t = idx[i] / NN;
        int y = t % MM;
        int b = t / MM;

        float xs = (float)x + f[i].x;
        float ys = (float)y + f[i].y;

        float x0f = floorf(xs);
        float y0f = floorf(ys);
        float wx = xs - x0f;
        float wy = ys - y0f;
        int x0 = (int)x0f;
        int y0 = (int)y0f;
        int x1 = x0 + 1;
        int y1 = y0 + 1;

        float wxm0 = ((unsigned)x0 < (unsigned)NN) ? (1.0f - wx) : 0.0f;
        float wxm1 = ((unsigned)x1 < (unsigned)NN) ? wx : 0.0f;
        float wym0 = ((unsigned)y0 < (unsigned)MM) ? (1.0f - wy) : 0.0f;
        float wym1 = ((unsigned)y1 < (unsigned)MM) ? wy : 0.0f;

        int xc0 = min(max(x0, 0), NN - 1);
        int xc1 = min(max(x1, 0), NN - 1);
        int yc0 = min(max(y0, 0), MM - 1);
        int yc1 = min(max(y1, 0), MM - 1);

        o00[i] = yc0 * NN + xc0;
        o01[i] = yc0 * NN + xc1;
        o10[i] = yc1 * NN + xc0;
        o11[i] = yc1 * NN + xc1;
        w00[i] = wym0 * wxm0;
        w01[i] = wym0 * wxm1;
        w10[i] = wym1 * wxm0;
        w11[i] = wym1 * wxm1;
        pbase[i] = (size_t)(2 * b) * MN;
    }

    // issue all 32 gathers unconditionally, front-batched for MLP
    float vA00[ILP], vA01[ILP], vA10[ILP], vA11[ILP];
    float vB00[ILP], vB01[ILP], vB10[ILP], vB11[ILP];
#pragma unroll
    for (int i = 0; i < ILP; i++) {
        const float* pA = image + pbase[i];
        const float* pB = pA + MN;
        vA00[i] = __ldg(pA + o00[i]);
        vA01[i] = __ldg(pA + o01[i]);
        vA10[i] = __ldg(pA + o10[i]);
        vA11[i] = __ldg(pA + o11[i]);
        vB00[i] = __ldg(pB + o00[i]);
        vB01[i] = __ldg(pB + o01[i]);
        vB10[i] = __ldg(pB + o10[i]);
        vB11[i] = __ldg(pB + o11[i]);
    }

#pragma unroll
    for (int i = 0; i < ILP; i++) {
        float accA = vA00[i] * w00[i] + vA01[i] * w01[i]
                   + vA10[i] * w10[i] + vA11[i] * w11[i];
        float accB = vB00[i] * w00[i] + vB01[i] * w01[i]
                   + vB10[i] * w10[i] + vB11[i] * w11[i];
        // out offset: plane base + (idx % MN)
        int po = idx[i] - (int)(pbase[i] >> 1);  // idx - b*MN = y*NN + x
        __stcs(out + pbase[i] + po, accA);       // streaming stores
        __stcs(out + pbase[i] + MN + po, accB);
    }
}

extern "C" void kernel_launch(void* const* d_in, const int* in_sizes, int n_in,
                              void* d_out, int out_size)
{
    const float*  image = (const float*)d_in[0];
    const float2* flow  = (const float2*)d_in[1];
    float* out = (float*)d_out;

    int total = out_size / 2;                       // B*M*N pixels
    int threads = 256;
    int blocks = total / (threads * ILP);           // exact: 9216
    warp_kernel<<<blocks, threads>>>(image, flow, out);
}

// round 8
// speedup vs baseline: 1.2179x; 1.0321x over previous
#include <cuda_runtime.h>

// Reference semantics: image (B,M,N,2) raw-reinterpreted as (2B,M,N) planes;
// flow2[p] = flow[p>>1]; out[p*MN + y*N + x] = bilinear(plane p, x+dx, y+dy),
// zero outside bounds. Row-aligned mapping: block = 4 rows of one batch,
// blockDim = 384 (one row), x = threadIdx.x, so NO per-pixel div/mod.
// Each thread: 4 pixels (same x, rows y0..y0+3), both planes.
// Grid = 64 batches * 96 row-groups = 6144 blocks.

#define MM 384
#define NN 384
#define MN (MM * NN)
#define ROWS 4

__global__ __launch_bounds__(384) void warp_kernel(
    const float*  __restrict__ image,  // 2B*MN floats (raw)
    const float2* __restrict__ flow,   // B*MN float2
    float*        __restrict__ out)    // 2B*MN floats (raw)
{
    int bid = blockIdx.x;
    int b   = bid / 96;            // uniform per block
    int y0  = (bid - b * 96) * ROWS;
    int x   = threadIdx.x;

    const size_t pbase = (size_t)(2 * b) * MN;        // plane-A base
    const float2* frow = flow + (size_t)b * MN + y0 * NN + x;

    // flow loads for 4 rows (independent, streaming)
    float2 f[ROWS];
#pragma unroll
    for (int i = 0; i < ROWS; i++)
        f[i] = __ldcs(frow + i * NN);

    int   o00[ROWS], o01[ROWS], o10[ROWS], o11[ROWS];
    float w00[ROWS], w01[ROWS], w10[ROWS], w11[ROWS];

#pragma unroll
    for (int i = 0; i < ROWS; i++) {
        float xs = (float)x + f[i].x;
        float ys = (float)(y0 + i) + f[i].y;

        float x0f = floorf(xs);
        float y0f = floorf(ys);
        float wx = xs - x0f;
        float wy = ys - y0f;
        int xi0 = (int)x0f;
        int yi0 = (int)y0f;
        int xi1 = xi0 + 1;
        int yi1 = yi0 + 1;

        float wxm0 = ((unsigned)xi0 < (unsigned)NN) ? (1.0f - wx) : 0.0f;
        float wxm1 = ((unsigned)xi1 < (unsigned)NN) ? wx : 0.0f;
        float wym0 = ((unsigned)yi0 < (unsigned)MM) ? (1.0f - wy) : 0.0f;
        float wym1 = ((unsigned)yi1 < (unsigned)MM) ? wy : 0.0f;

        int xc0 = min(max(xi0, 0), NN - 1);
        int xc1 = min(max(xi1, 0), NN - 1);
        int yc0 = min(max(yi0, 0), MM - 1);
        int yc1 = min(max(yi1, 0), MM - 1);

        o00[i] = yc0 * NN + xc0;
        o01[i] = yc0 * NN + xc1;
        o10[i] = yc1 * NN + xc0;
        o11[i] = yc1 * NN + xc1;
        w00[i] = wym0 * wxm0;
        w01[i] = wym0 * wxm1;
        w10[i] = wym1 * wxm0;
        w11[i] = wym1 * wxm1;
    }

    const float* pA = image + pbase;
    const float* pB = pA + MN;

    // front-batch all 32 gathers
    float vA00[ROWS], vA01[ROWS], vA10[ROWS], vA11[ROWS];
    float vB00[ROWS], vB01[ROWS], vB10[ROWS], vB11[ROWS];
#pragma unroll
    for (int i = 0; i < ROWS; i++) {
        vA00[i] = __ldg(pA + o00[i]);
        vA01[i] = __ldg(pA + o01[i]);
        vA10[i] = __ldg(pA + o10[i]);
        vA11[i] = __ldg(pA + o11[i]);
        vB00[i] = __ldg(pB + o00[i]);
        vB01[i] = __ldg(pB + o01[i]);
        vB10[i] = __ldg(pB + o10[i]);
        vB11[i] = __ldg(pB + o11[i]);
    }

    float* oA = out + pbase + y0 * NN + x;
    float* oB = oA + MN;
#pragma unroll
    for (int i = 0; i < ROWS; i++) {
        float accA = vA00[i] * w00[i] + vA01[i] * w01[i]
                   + vA10[i] * w10[i] + vA11[i] * w11[i];
        float accB = vB00[i] * w00[i] + vB01[i] * w01[i]
                   + vB10[i] * w10[i] + vB11[i] * w11[i];
        __stcs(oA + i * NN, accA);
        __stcs(oB + i * NN, accB);
    }
}

extern "C" void kernel_launch(void* const* d_in, const int* in_sizes, int n_in,
                              void* d_out, int out_size)
{
    const float*  image = (const float*)d_in[0];
    const float2* flow  = (const float2*)d_in[1];
    float* out = (float*)d_out;

    // B = out_size / (2*MN) ; grid = B * (MM/ROWS)
    int B = out_size / (2 * MN);
    int blocks = B * (MM / ROWS);   // 64 * 96 = 6144
    warp_kernel<<<blocks, 384>>>(image, flow, out);
}